// round 14
// baseline (speedup 1.0000x reference)
#include <cuda_runtime.h>
#include <cstdint>

#define BB 8
#define TT 12
#define NNODE 400
#define DD 128
#define HH 8
#define HDIM 16
#define UU 16
#define CC 64
#define FFD 2048
#define MROWS (BB*TT*NNODE)   /* 38400 */
#define BTN (BB*TT)           /* 96 */

// ---- single scratch arena (no allocations allowed) ----
#define CHSZ 4915200u         /* MROWS*DD */
#define OFF_HID   (13u*CHSZ)
#define OFF_KP    (OFF_HID + (size_t)MROWS*FFD)
#define OFF_VP    (OFF_KP + (size_t)BTN*CC*DD)
#define OFF_SENX  (OFF_VP + (size_t)BTN*CC*DD)
#define SCRATCH_TOTAL (OFF_SENX + (size_t)NNODE*DD)

__device__ float g_scratch[SCRATCH_TOTAL];
__device__ float g_zerobias[FFD];   // static zero-init

// ---------------- tf32 / f32x2 helpers --------------------------------------
__device__ __forceinline__ unsigned cvt_tf32(float v) {
    unsigned r;
    asm("cvt.rna.tf32.f32 %0, %1;" : "=r"(r) : "f"(v));
    return r;
}
__device__ __forceinline__ void mma_tf32(float& c0, float& c1, float& c2, float& c3,
                                         unsigned a0, unsigned a1, unsigned a2, unsigned a3,
                                         unsigned b0, unsigned b1) {
    asm("mma.sync.aligned.m16n8k8.row.col.f32.tf32.tf32.f32 "
        "{%0,%1,%2,%3}, {%4,%5,%6,%7}, {%8,%9}, {%0,%1,%2,%3};"
        : "+f"(c0), "+f"(c1), "+f"(c2), "+f"(c3)
        : "r"(a0), "r"(a1), "r"(a2), "r"(a3), "r"(b0), "r"(b1));
}
__device__ __forceinline__ unsigned sm_u32(const void* p) {
    return (unsigned)__cvta_generic_to_shared(p);
}
__device__ __forceinline__ void cp16(unsigned dst, const float* src, int srcsize) {
    asm volatile("cp.async.ca.shared.global [%0], [%1], 16, %2;"
                 :: "r"(dst), "l"(src), "r"(srcsize));
}
__device__ __forceinline__ void cp_commit() {
    asm volatile("cp.async.commit_group;");
}
__device__ __forceinline__ void cp_wait1() {
    asm volatile("cp.async.wait_group 1;");
}
__device__ __forceinline__ unsigned long long pack2(float lo, float hi) {
    unsigned long long r;
    asm("mov.b64 %0, {%1, %2};" : "=l"(r)
        : "r"(__float_as_uint(lo)), "r"(__float_as_uint(hi)));
    return r;
}
__device__ __forceinline__ void unpack2(unsigned long long v, float& lo, float& hi) {
    unsigned a, b;
    asm("mov.b64 {%0, %1}, %2;" : "=r"(a), "=r"(b) : "l"(v));
    lo = __uint_as_float(a); hi = __uint_as_float(b);
}
__device__ __forceinline__ void fma2(unsigned long long& d,
                                     unsigned long long a, unsigned long long b) {
    asm("fma.rn.f32x2 %0, %1, %2, %0;" : "+l"(d) : "l"(a), "l"(b));
}

// ---------------- tf32 GEMM core (R8 known-best: 3-stage cp.async) ---------
#define AS_WORDS (128 * 20)
#define BS_WORDS (16 * 136)
#define STAGE_WORDS (AS_WORDS + BS_WORDS)
#define NSTAGE 3
#define GEMM_SMEM (STAGE_WORDS * NSTAGE * 4) /* 56832 B */

__device__ __forceinline__ void gemm_core(
    unsigned* smem_u,
    const float* __restrict__ A, const float* __restrict__ W,
    const float* __restrict__ bias, float* __restrict__ C,
    int M, int N, int kchunk, int lda, int relu, int m0, int n0, int k0)
{
    int tid = threadIdx.x;
    int warp = tid >> 5, lane = tid & 31;
    int g = lane >> 2, tg = lane & 3;
    int wm = warp >> 2, wn = warp & 3;            // 2 x 4
    int nk = kchunk >> 4;

    int arow = tid >> 1, akoff = (tid & 1) * 8;
    int asz = (m0 + arow < M) ? 16 : 0;
    int bc0 = tid * 2;
    int br0 = bc0 >> 5, bn0 = (bc0 & 31) * 4;
    int br1 = (bc0 + 1) >> 5, bn1 = ((bc0 + 1) & 31) * 4;

    float acc[4][4][4];
#pragma unroll
    for (int i = 0; i < 4; i++)
#pragma unroll
        for (int j = 0; j < 4; j++)
#pragma unroll
            for (int r = 0; r < 4; r++) acc[i][j][r] = 0.f;

#define ISSUE(kt) do {                                                        \
        unsigned* Asb = smem_u + ((kt) % NSTAGE) * STAGE_WORDS;               \
        unsigned* Bsb = Asb + AS_WORDS;                                       \
        const float* asrc = &A[(size_t)(m0 + arow) * lda + k0 + (kt) * 16 + akoff]; \
        cp16(sm_u32(&Asb[arow * 20 + akoff]),     asrc,     asz);             \
        cp16(sm_u32(&Asb[arow * 20 + akoff + 4]), asrc + 4, asz);             \
        cp16(sm_u32(&Bsb[br0 * 136 + bn0]),                                   \
             &W[(size_t)(k0 + (kt) * 16 + br0) * N + n0 + bn0], 16);          \
        cp16(sm_u32(&Bsb[br1 * 136 + bn1]),                                   \
             &W[(size_t)(k0 + (kt) * 16 + br1) * N + n0 + bn1], 16);          \
    } while (0)

#pragma unroll
    for (int s = 0; s < NSTAGE - 1; s++) {
        if (s < nk) ISSUE(s);
        cp_commit();
    }

    for (int kt = 0; kt < nk; kt++) {
        if (kt + NSTAGE - 1 < nk) ISSUE(kt + NSTAGE - 1);
        cp_commit();
        cp_wait1();
        __syncthreads();

        const unsigned* as = smem_u + (kt % NSTAGE) * STAGE_WORDS;
        const unsigned* bs = as + AS_WORDS;

#pragma unroll
        for (int step = 0; step < 2; step++) {
            int ko = step * 8;
            unsigned af[4][4];
#pragma unroll
            for (int ma = 0; ma < 4; ma++) {
                int r = wm * 64 + ma * 16 + g;
                af[ma][0] = cvt_tf32(__uint_as_float(as[r * 20 + ko + tg]));
                af[ma][1] = cvt_tf32(__uint_as_float(as[(r + 8) * 20 + ko + tg]));
                af[ma][2] = cvt_tf32(__uint_as_float(as[r * 20 + ko + tg + 4]));
                af[ma][3] = cvt_tf32(__uint_as_float(as[(r + 8) * 20 + ko + tg + 4]));
            }
            unsigned bf[4][2];
#pragma unroll
            for (int na = 0; na < 4; na++) {
                int nc = wn * 32 + na * 8 + g;
                bf[na][0] = cvt_tf32(__uint_as_float(bs[(ko + tg) * 136 + nc]));
                bf[na][1] = cvt_tf32(__uint_as_float(bs[(ko + tg + 4) * 136 + nc]));
            }
#pragma unroll
            for (int ma = 0; ma < 4; ma++)
#pragma unroll
                for (int na = 0; na < 4; na++)
                    mma_tf32(acc[ma][na][0], acc[ma][na][1], acc[ma][na][2], acc[ma][na][3],
                             af[ma][0], af[ma][1], af[ma][2], af[ma][3],
                             bf[na][0], bf[na][1]);
        }
        __syncthreads();
    }
#undef ISSUE

#pragma unroll
    for (int ma = 0; ma < 4; ma++) {
        int r0 = m0 + wm * 64 + ma * 16 + g;
        int r1 = r0 + 8;
#pragma unroll
        for (int na = 0; na < 4; na++) {
            int col = n0 + wn * 32 + na * 8 + tg * 2;
            float b0 = bias[col], b1 = bias[col + 1];
            float o0 = acc[ma][na][0] + b0, o1 = acc[ma][na][1] + b1;
            float o2 = acc[ma][na][2] + b0, o3 = acc[ma][na][3] + b1;
            if (relu) {
                o0 = fmaxf(o0, 0.f); o1 = fmaxf(o1, 0.f);
                o2 = fmaxf(o2, 0.f); o3 = fmaxf(o3, 0.f);
            }
            if (r0 < M) *(float2*)&C[(size_t)r0 * N + col] = make_float2(o0, o1);
            if (r1 < M) *(float2*)&C[(size_t)r1 * N + col] = make_float2(o2, o3);
        }
    }
}

// generic wrapper (split-K via blockIdx.z)
__global__ __launch_bounds__(256, 2) void gemm_tf32_kernel(
    const float* __restrict__ A, const float* __restrict__ W,
    const float* __restrict__ bias, float* __restrict__ C,
    int M, int N, int kchunk, int lda, size_t zstride, int relu)
{
    extern __shared__ unsigned smem_u[];
    const float* bp = (blockIdx.z == 0) ? bias : g_zerobias;
    gemm_core(smem_u, A, W, bp, C + (size_t)blockIdx.z * zstride,
              M, N, kchunk, lda, relu,
              blockIdx.x * 128, blockIdx.y * 128, blockIdx.z * kchunk);
}

// fused multi-GEMM wrapper: per-slot A/W/bias/C, N=K=lda=128
struct MultiArgs {
    const float* A[7];
    const float* W[7];
    const float* Bv[7];
    float* C[7];
};
__global__ __launch_bounds__(256, 2) void gemm_multi_kernel(MultiArgs ma, int M)
{
    extern __shared__ unsigned smem_u[];
    int j = blockIdx.y;
    gemm_core(smem_u, ma.A[j], ma.W[j], ma.Bv[j], ma.C[j],
              M, DD, DD, DD, 0, blockIdx.x * 128, 0, 0);
}

// ---------------- warp-per-row LayerNorm family ----------------------------
__device__ __forceinline__ float warp_sum(float v) {
#pragma unroll
    for (int o = 16; o; o >>= 1) v += __shfl_xor_sync(0xffffffffu, v, o);
    return v;
}
__device__ __forceinline__ float block_sum_128(float v, float* sb) {
#pragma unroll
    for (int o = 16; o; o >>= 1) v += __shfl_xor_sync(0xffffffffu, v, o);
    if ((threadIdx.x & 31) == 0) sb[threadIdx.x >> 5] = v;
    __syncthreads();
    float r = sb[0] + sb[1] + sb[2] + sb[3];
    __syncthreads();
    return r;
}

__global__ __launch_bounds__(256) void lnsum4_kernel(
    const float* __restrict__ x, const float* __restrict__ a,
    const float* __restrict__ bp, const float* __restrict__ c,
    const float* __restrict__ g, const float* __restrict__ be,
    float* __restrict__ outp)
{
    int warp = threadIdx.x >> 5, lane = threadIdx.x & 31;
    size_t row = (size_t)blockIdx.x * 8 + warp;
    size_t i = row * 128 + lane * 4;
    float4 v0 = *(const float4*)&x[i];
    float4 v1 = *(const float4*)&a[i];
    float4 v2 = *(const float4*)&bp[i];
    float4 v3 = *(const float4*)&c[i];
    float vx = v0.x + v1.x + v2.x + v3.x;
    float vy = v0.y + v1.y + v2.y + v3.y;
    float vz = v0.z + v1.z + v2.z + v3.z;
    float vw = v0.w + v1.w + v2.w + v3.w;
    float mean = warp_sum(vx + vy + vz + vw) * (1.f / 128.f);
    float dx = vx - mean, dy = vy - mean, dz = vz - mean, dw = vw - mean;
    float var = warp_sum(dx*dx + dy*dy + dz*dz + dw*dw) * (1.f / 128.f);
    float rs = rsqrtf(var + 1e-5f);
    float4 gg = *(const float4*)&g[lane * 4];
    float4 bb = *(const float4*)&be[lane * 4];
    *(float4*)&outp[i] = make_float4(dx*rs*gg.x + bb.x, dy*rs*gg.y + bb.y,
                                     dz*rs*gg.z + bb.z, dw*rs*gg.w + bb.w);
}

// attn2 = LN(sum of 4 split-K partials + s); spin = attn2 * senx[row%NNODE]
__global__ __launch_bounds__(256) void ln2mul_kernel(
    const float* __restrict__ parts, const float* __restrict__ s,
    const float* __restrict__ senx,
    const float* __restrict__ g, const float* __restrict__ be,
    float* __restrict__ attn2, float* __restrict__ spin)
{
    int warp = threadIdx.x >> 5, lane = threadIdx.x & 31;
    size_t row = (size_t)blockIdx.x * 8 + warp;
    size_t i = row * 128 + lane * 4;
    float4 sv = *(const float4*)&s[i];
    float vx = sv.x, vy = sv.y, vz = sv.z, vw = sv.w;
#pragma unroll
    for (int c = 0; c < 4; c++) {
        float4 p = *(const float4*)&parts[i + (size_t)c * CHSZ];
        vx += p.x; vy += p.y; vz += p.z; vw += p.w;
    }
    float mean = warp_sum(vx + vy + vz + vw) * (1.f / 128.f);
    float dx = vx - mean, dy = vy - mean, dz = vz - mean, dw = vw - mean;
    float var = warp_sum(dx*dx + dy*dy + dz*dz + dw*dw) * (1.f / 128.f);
    float rs = rsqrtf(var + 1e-5f);
    float4 gg = *(const float4*)&g[lane * 4];
    float4 bb = *(const float4*)&be[lane * 4];
    float ox = dx*rs*gg.x + bb.x, oy = dy*rs*gg.y + bb.y;
    float oz = dz*rs*gg.z + bb.z, ow = dw*rs*gg.w + bb.w;
    *(float4*)&attn2[i] = make_float4(ox, oy, oz, ow);
    float4 sx = *(const float4*)&senx[(size_t)(row % NNODE) * 128 + lane * 4];
    *(float4*)&spin[i] = make_float4(ox*sx.x, oy*sx.y, oz*sx.z, ow*sx.w);
}

// out = attn2 + LN(sum of 4 split-K partials)
__global__ __launch_bounds__(256) void final_kernel(
    const float* __restrict__ parts, const float* __restrict__ attn2,
    const float* __restrict__ g, const float* __restrict__ be,
    float* __restrict__ outp)
{
    int warp = threadIdx.x >> 5, lane = threadIdx.x & 31;
    size_t row = (size_t)blockIdx.x * 8 + warp;
    size_t i = row * 128 + lane * 4;
    float vx = 0.f, vy = 0.f, vz = 0.f, vw = 0.f;
#pragma unroll
    for (int c = 0; c < 4; c++) {
        float4 p = *(const float4*)&parts[i + (size_t)c * CHSZ];
        vx += p.x; vy += p.y; vz += p.z; vw += p.w;
    }
    float mean = warp_sum(vx + vy + vz + vw) * (1.f / 128.f);
    float dx = vx - mean, dy = vy - mean, dz = vz - mean, dw = vw - mean;
    float var = warp_sum(dx*dx + dy*dy + dz*dz + dw*dw) * (1.f / 128.f);
    float rs = rsqrtf(var + 1e-5f);
    float4 gg = *(const float4*)&g[lane * 4];
    float4 bb = *(const float4*)&be[lane * 4];
    float4 a2 = *(const float4*)&attn2[i];
    *(float4*)&outp[i] = make_float4(a2.x + dx*rs*gg.x + bb.x, a2.y + dy*rs*gg.y + bb.y,
                                     a2.z + dz*rs*gg.z + bb.z, a2.w + dw*rs*gg.w + bb.w);
}

// ---------------- fused sen path: spe@sw+b -> LN -> @shw+b -> edge ---------
__global__ __launch_bounds__(128) void sen_kernel(
    const float* __restrict__ spe,
    const float* __restrict__ sw, const float* __restrict__ sb_,
    const float* __restrict__ shw, const float* __restrict__ shb,
    const float* __restrict__ lg, const float* __restrict__ lb_,
    const float* __restrict__ ew, const float* __restrict__ eb,
    float* __restrict__ senx, float* __restrict__ outtail)
{
    __shared__ float A[128], Bs[128], Cs[128];
    __shared__ float red[4];
    int n = blockIdx.x, t = threadIdx.x;
    int h = t >> 4, u = t & 15;

    A[t] = spe[(size_t)n * 128 + t];
    __syncthreads();

    float acc = sb_[t];
#pragma unroll 8
    for (int k = 0; k < 128; k++) acc = fmaf(A[k], sw[k * 128 + t], acc);

    float mean = block_sum_128(acc, red) * (1.f / 128.f);
    float d = acc - mean;
    float var = block_sum_128(d * d, red) * (1.f / 128.f);
    float sen = d * rsqrtf(var + 1e-5f) * lg[t] + lb_[t];
    Bs[t] = sen;
    __syncthreads();

    float el = shb[t];
#pragma unroll 8
    for (int k = 0; k < 128; k++) el = fmaf(Bs[k], shw[k * 128 + t], el);
    A[t] = el;
    __syncthreads();

    float eacc = eb[u];
#pragma unroll
    for (int k = 0; k < 16; k++) eacc = fmaf(A[k * 8 + h], ew[k * 16 + u], eacc);
    Bs[t] = eacc;
    __syncthreads();
    float mx = -1e30f;
#pragma unroll
    for (int hh = 0; hh < 8; hh++) mx = fmaxf(mx, Bs[hh * 16 + u]);
    float sume = 0.f;
#pragma unroll
    for (int hh = 0; hh < 8; hh++) sume += __expf(Bs[hh * 16 + u] - mx);
    float a = __expf(eacc - mx) / sume;
    Cs[t] = a;
    __syncthreads();
    float rs = 0.f;
#pragma unroll
    for (int uu = 0; uu < 16; uu++) rs += Cs[h * 16 + uu];
    float a2 = a / rs;
    __syncthreads();
    A[t] = a2;
    __syncthreads();
    float y = eb[16 + u];
#pragma unroll
    for (int k = 0; k < 16; k++) y = fmaf(A[h * 16 + k], ew[256 + k * 16 + u], y);
    senx[(size_t)n * 128 + t] = y;
    outtail[(size_t)n * 128 + t] = y;
}

// ---------------- adaptive avg pool over node axis -------------------------
__global__ void pool_kernel(const float* __restrict__ Kin, const float* __restrict__ Vin,
                            float* __restrict__ Kp, float* __restrict__ Vp)
{
    int bt = blockIdx.x, c = blockIdx.y, d = threadIdx.x;
    int s = (c * NNODE) / CC;
    int e = ((c + 1) * NNODE + CC - 1) / CC;
    float inv = 1.f / (float)(e - s);
    float ak = 0.f, av = 0.f;
    for (int n = s; n < e; n++) {
        ak += Kin[((size_t)bt * NNODE + n) * DD + d];
        av += Vin[((size_t)bt * NNODE + n) * DD + d];
    }
    Kp[((size_t)bt * CC + c) * DD + d] = ak * inv;
    Vp[((size_t)bt * CC + c) * DD + d] = av * inv;
}

// ---------------- dtw attention v2: f32x2 key pairs, 1 query/warp-pass -----
// 2 blocks/SM (regs <= 128), scale 0.25 folded into q (exact power of 2).
__global__ __launch_bounds__(256, 2) void attn_dtw_kernel(
    const float* __restrict__ Q, const float* __restrict__ K,
    const float* __restrict__ V, float* __restrict__ O)
{
    extern __shared__ float sm[];
    float* Qs = sm;               // 400*16
    float* Kt = sm + 6400;        // 16*416 (8B-aligned rows)
    float* Vt = sm + 6400 + 6656;
    int bt = blockIdx.x, h = blockIdx.y;
    size_t base = ((size_t)bt * NNODE) * DD + h * HDIM;
    int tid = threadIdx.x;
    for (int e = tid; e < NNODE * 4; e += 256) {
        int q = e >> 2, d4 = (e & 3) << 2;
        float4 qv = *(const float4*)&Q[base + (size_t)q * DD + d4];
        float4 kv = *(const float4*)&K[base + (size_t)q * DD + d4];
        float4 vv = *(const float4*)&V[base + (size_t)q * DD + d4];
        *(float4*)&Qs[q * 16 + d4] = qv;
        Kt[(d4 + 0) * 416 + q] = kv.x; Kt[(d4 + 1) * 416 + q] = kv.y;
        Kt[(d4 + 2) * 416 + q] = kv.z; Kt[(d4 + 3) * 416 + q] = kv.w;
        Vt[(d4 + 0) * 416 + q] = vv.x; Vt[(d4 + 1) * 416 + q] = vv.y;
        Vt[(d4 + 2) * 416 + q] = vv.z; Vt[(d4 + 3) * 416 + q] = vv.w;
    }
    __syncthreads();
    int warp = tid >> 5, lane = tid & 31;
    for (int q = warp; q < NNODE; q += 8) {
        // broadcast-packed query, 0.25 scale folded (exact)
        unsigned long long qb[16];
#pragma unroll
        for (int d = 0; d < 16; d++) {
            float qv = Qs[q * 16 + d] * 0.25f;
            qb[d] = pack2(qv, qv);
        }
        // scores over key pairs: lane owns keys 2*(lane+32i), +1
        unsigned long long sp[7];
        float mx = -1e30f;
#pragma unroll
        for (int i = 0; i < 7; i++) {
            int j0 = (lane + (i << 5)) << 1;
            unsigned long long s2 = pack2(-1e30f, -1e30f);
            if (j0 < NNODE) {
                s2 = 0ull;
#pragma unroll
                for (int d = 0; d < 16; d++)
                    fma2(s2, qb[d], *(const unsigned long long*)&Kt[d * 416 + j0]);
                float lo, hi; unpack2(s2, lo, hi);
                mx = fmaxf(mx, fmaxf(lo, hi));
            }
            sp[i] = s2;
        }
#pragma unroll
        for (int o = 16; o; o >>= 1)
            mx = fmaxf(mx, __shfl_xor_sync(0xffffffffu, mx, o));
        float l = 0.f;
#pragma unroll
        for (int i = 0; i < 7; i++) {
            float lo, hi; unpack2(sp[i], lo, hi);
            float pa = __expf(lo - mx), pb = __expf(hi - mx);
            sp[i] = pack2(pa, pb);
            l += pa + pb;
        }
#pragma unroll
        for (int o = 16; o; o >>= 1)
            l += __shfl_xor_sync(0xffffffffu, l, o);
        // PV with packed pairs
        unsigned long long accp[16];
#pragma unroll
        for (int d = 0; d < 16; d++) accp[d] = 0ull;
#pragma unroll
        for (int i = 0; i < 7; i++) {
            int j0 = (lane + (i << 5)) << 1;
            if (j0 < NNODE) {
#pragma unroll
                for (int d = 0; d < 16; d++)
                    fma2(accp[d], sp[i], *(const unsigned long long*)&Vt[d * 416 + j0]);
            }
        }
        float acc[16];
#pragma unroll
        for (int d = 0; d < 16; d++) {
            float lo, hi; unpack2(accp[d], lo, hi);
            acc[d] = lo + hi;
#pragma unroll
            for (int o = 16; o; o >>= 1)
                acc[d] += __shfl_xor_sync(0xffffffffu, acc[d], o);
        }
        if (lane < 16)
            O[base + (size_t)q * DD + lane] = acc[lane] / l;
    }
}

// ---------------- pooled attention: 64 keys + positional bias --------------
__global__ __launch_bounds__(256) void attn_adp_kernel(
    const float* __restrict__ Q, const float* __restrict__ Kp,
    const float* __restrict__ Vp, const float* __restrict__ pos,
    float* __restrict__ O)
{
    __shared__ float Qs[NNODE * 16];
    __shared__ float Kt[16 * 64];
    __shared__ float Vt[16 * 64];
    int bt = blockIdx.x, h = blockIdx.y, tid = threadIdx.x;
    size_t qbase = ((size_t)bt * NNODE) * DD + h * HDIM;
    size_t kbase = ((size_t)bt * CC) * DD + h * HDIM;
    for (int e = tid; e < NNODE * 4; e += 256) {
        int q = e >> 2, d4 = (e & 3) << 2;
        *(float4*)&Qs[q * 16 + d4] = *(const float4*)&Q[qbase + (size_t)q * DD + d4];
    }
    {
        int c = tid >> 2, d4 = (tid & 3) << 2;
        float4 kv = *(const float4*)&Kp[kbase + (size_t)c * DD + d4];
        float4 vv = *(const float4*)&Vp[kbase + (size_t)c * DD + d4];
        Kt[(d4 + 0) * 64 + c] = kv.x; Kt[(d4 + 1) * 64 + c] = kv.y;
        Kt[(d4 + 2) * 64 + c] = kv.z; Kt[(d4 + 3) * 64 + c] = kv.w;
        Vt[(d4 + 0) * 64 + c] = vv.x; Vt[(d4 + 1) * 64 + c] = vv.y;
        Vt[(d4 + 2) * 64 + c] = vv.z; Vt[(d4 + 3) * 64 + c] = vv.w;
    }
    __syncthreads();
    int warp = tid >> 5, lane = tid & 31;
    for (int pp = warp; pp < NNODE / 2; pp += 8) {
        int qa = pp * 2;
        float qva[16], qvb[16];
#pragma unroll
        for (int d = 0; d < 16; d++) {
            qva[d] = Qs[qa * 16 + d];
            qvb[d] = Qs[qa * 16 + 16 + d];
        }
        float s00 = 0.f, s01 = 0.f, s10 = 0.f, s11 = 0.f;
#pragma unroll
        for (int d = 0; d < 16; d++) {
            float k0 = Kt[d * 64 + lane], k1 = Kt[d * 64 + lane + 32];
            s00 = fmaf(qva[d], k0, s00); s01 = fmaf(qva[d], k1, s01);
            s10 = fmaf(qvb[d], k0, s10); s11 = fmaf(qvb[d], k1, s11);
        }
        s00 = s00 * 0.25f + pos[(size_t)qa * 64 + lane];
        s01 = s01 * 0.25f + pos[(size_t)qa * 64 + lane + 32];
        s10 = s10 * 0.25f + pos[(size_t)(qa + 1) * 64 + lane];
        s11 = s11 * 0.25f + pos[(size_t)(qa + 1) * 64 + lane + 32];
        float mxa = fmaxf(s00, s01), mxb = fmaxf(s10, s11);
#pragma unroll
        for (int o = 16; o; o >>= 1) {
            mxa = fmaxf(mxa, __shfl_xor_sync(0xffffffffu, mxa, o));
            mxb = fmaxf(mxb, __shfl_xor_sync(0xffffffffu, mxb, o));
        }
        float p00 = __expf(s00 - mxa), p01 = __expf(s01 - mxa);
        float p10 = __expf(s10 - mxb), p11 = __expf(s11 - mxb);
        float la = p00 + p01, lb = p10 + p11;
#pragma unroll
        for (int o = 16; o; o >>= 1) {
            la += __shfl_xor_sync(0xffffffffu, la, o);
            lb += __shfl_xor_sync(0xffffffffu, lb, o);
        }
        float acca[16], accb[16];
#pragma unroll
        for (int d = 0; d < 16; d++) {
            float v0 = Vt[d * 64 + lane], v1 = Vt[d * 64 + lane + 32];
            acca[d] = p00 * v0 + p01 * v1;
            accb[d] = p10 * v0 + p11 * v1;
        }
#pragma unroll
        for (int d = 0; d < 16; d++) {
#pragma unroll
            for (int o = 16; o; o >>= 1) {
                acca[d] += __shfl_xor_sync(0xffffffffu, acca[d], o);
                accb[d] += __shfl_xor_sync(0xffffffffu, accb[d], o);
            }
        }
        if (lane < 16) {
            O[qbase + (size_t)qa * DD + lane]       = acca[lane] / la;
            O[qbase + (size_t)(qa + 1) * DD + lane] = accb[lane] / lb;
        }
    }
}

// ---------------- GEANet node path (reshape-of-transpose perm) -------------
__global__ void node_kernel(const float* __restrict__ share, const float* __restrict__ nw,
                            const float* __restrict__ nb, float* __restrict__ extra)
{
    __shared__ float s0[128], s1[128], s2[128];
    int row = blockIdx.x;
    int b = row / (TT * NNODE), p = row % (TT * NNODE);
    int nn = p / TT, ll = p % TT;
    int t = threadIdx.x;
    int h = t >> 4, u = t & 15;
    s0[t] = share[(((size_t)b * TT + ll) * NNODE + nn) * 128 + t];
    __syncthreads();
    float acc = nb[u];
#pragma unroll
    for (int k = 0; k < 16; k++) acc = fmaf(s0[h * 16 + k], nw[k * 16 + u], acc);
    s1[t] = acc;
    __syncthreads();
    float mx = -1e30f;
#pragma unroll
    for (int hh = 0; hh < 8; hh++) mx = fmaxf(mx, s1[hh * 16 + u]);
    float sume = 0.f;
#pragma unroll
    for (int hh = 0; hh < 8; hh++) sume += __expf(s1[hh * 16 + u] - mx);
    float a = __expf(acc - mx) / sume;
    s2[t] = a;
    __syncthreads();
    float rs = 0.f;
#pragma unroll
    for (int uu = 0; uu < 16; uu++) rs += s2[h * 16 + uu];
    float a2 = a / rs;
    __syncthreads();
    s0[t] = a2;
    __syncthreads();
    float y = nb[16 + u];
#pragma unroll
    for (int k = 0; k < 16; k++) y = fmaf(s0[h * 16 + k], nw[256 + k * 16 + u], y);
    extra[(size_t)row * 128 + t] = y;
}

// ---------------- host orchestration ---------------------------------------
extern "C" void kernel_launch(void* const* d_in, const int* in_sizes, int n_in,
                              void* d_out, int out_size)
{
    const float* x         = (const float*)d_in[0];
    const float* spe       = (const float*)d_in[1];
    const float* dtw_qkv_w = (const float*)d_in[2];
    const float* dtw_qkv_b = (const float*)d_in[3];
    const float* dtw_out_w = (const float*)d_in[4];
    const float* dtw_out_b = (const float*)d_in[5];
    const float* att_qkv_w = (const float*)d_in[6];
    const float* att_qkv_b = (const float*)d_in[7];
    const float* att_out_w = (const float*)d_in[8];
    const float* att_out_b = (const float*)d_in[9];
    const float* adp_pos   = (const float*)d_in[10];
    const float* share_w   = (const float*)d_in[11];
    const float* share_b   = (const float*)d_in[12];
    const float* node_w    = (const float*)d_in[13];
    const float* node_b    = (const float*)d_in[14];
    const float* edge_w    = (const float*)d_in[15];
    const float* edge_b    = (const float*)d_in[16];
    const float* spatial_w = (const float*)d_in[17];
    const float* spatial_b = (const float*)d_in[18];
    const float* ff1w1     = (const float*)d_in[19];
    const float* ff1b1     = (const float*)d_in[20];
    const float* ff1w2     = (const float*)d_in[21];
    const float* ff1b2     = (const float*)d_in[22];
    const float* ff2w1     = (const float*)d_in[23];
    const float* ff2b1     = (const float*)d_in[24];
    const float* ff2w2     = (const float*)d_in[25];
    const float* ff2b2     = (const float*)d_in[26];
    const float* lns       = (const float*)d_in[27];
    const float* lnb       = (const float*)d_in[28];
    float* out = (float*)d_out;

    float* g = nullptr;
    { void* p; cudaGetSymbolAddress(&p, g_scratch); g = (float*)p; }
    float* PART = g + 0u * CHSZ;           // 4 split-K partials (chunks 0-3)
    float* Q1   = g + 0u * CHSZ;
    float* K1   = g + 1u * CHSZ;
    float* V1   = g + 2u * CHSZ;
    float* Q2   = g + 3u * CHSZ;
    float* K2   = g + 4u * CHSZ;
    float* V2   = g + 5u * CHSZ;
    float* SHR  = g + 6u * CHSZ;
    float* DTW  = g + 7u * CHSZ;
    float* OA   = g + 8u * CHSZ;
    float* B1   = g + 9u * CHSZ;
    float* B2   = g + 10u * CHSZ;
    float* B3   = g + 11u * CHSZ;
    float* B4   = g + 12u * CHSZ;
    float* HID  = g + OFF_HID;
    float* KP   = g + OFF_KP;
    float* VP   = g + OFF_VP;
    float* SENX = g + OFF_SENX;

    cudaFuncSetAttribute(attn_dtw_kernel,
                         cudaFuncAttributeMaxDynamicSharedMemorySize, 78848);
    cudaFuncSetAttribute(gemm_tf32_kernel,
                         cudaFuncAttributeMaxDynamicSharedMemorySize, GEMM_SMEM);
    cudaFuncSetAttribute(gemm_multi_kernel,
                         cudaFuncAttributeMaxDynamicSharedMemorySize, GEMM_SMEM);

#define GEMM(A_, W_, Bi_, C_, M_, N_, K_, LDA_, R_) \
    gemm_tf32_kernel<<<dim3(((M_) + 127) / 128, (N_) / 128, 1), 256, GEMM_SMEM>>>( \
        A_, W_, Bi_, C_, M_, N_, K_, LDA_, 0, R_)

    // fused QKV projections + GEANet share (one launch)
    {
        MultiArgs ma;
        for (int j = 0; j < 7; j++) ma.A[j] = x;
        ma.W[0] = dtw_qkv_w + 0 * DD * DD; ma.Bv[0] = dtw_qkv_b + 0 * DD; ma.C[0] = Q1;
        ma.W[1] = dtw_qkv_w + 1 * DD * DD; ma.Bv[1] = dtw_qkv_b + 1 * DD; ma.C[1] = K1;
        ma.W[2] = dtw_qkv_w + 2 * DD * DD; ma.Bv[2] = dtw_qkv_b + 2 * DD; ma.C[2] = V1;
        ma.W[3] = att_qkv_w + 0 * DD * DD; ma.Bv[3] = att_qkv_b + 0 * DD; ma.C[3] = Q2;
        ma.W[4] = att_qkv_w + 1 * DD * DD; ma.Bv[4] = att_qkv_b + 1 * DD; ma.C[4] = K2;
        ma.W[5] = att_qkv_w + 2 * DD * DD; ma.Bv[5] = att_qkv_b + 2 * DD; ma.C[5] = V2;
        ma.W[6] = share_w;                 ma.Bv[6] = share_b;            ma.C[6] = SHR;
        gemm_multi_kernel<<<dim3(MROWS / 128, 7), 256, GEMM_SMEM>>>(ma, MROWS);
    }

    // fused sen path
    sen_kernel<<<NNODE, 128>>>(spe, spatial_w, spatial_b, share_w, share_b,
                               lns + 3 * 128, lnb + 3 * 128, edge_w, edge_b,
                               SENX, out + (size_t)MROWS * DD);

    // GEANet node path
    node_kernel<<<MROWS, 128>>>(SHR, node_w, node_b, B1);

    // attentions (dtw -> B2, pooled -> B3), then merged dual out-projection
    attn_dtw_kernel<<<dim3(BTN, HH), 256, 78848>>>(Q1, K1, V1, B2);
    pool_kernel<<<dim3(BTN, CC), 128>>>(K2, V2, KP, VP);
    attn_adp_kernel<<<dim3(BTN, HH), 256>>>(Q2, KP, VP, adp_pos, B3);
    {
        MultiArgs ma;
        ma.A[0] = B2; ma.W[0] = dtw_out_w; ma.Bv[0] = dtw_out_b; ma.C[0] = DTW;
        ma.A[1] = B3; ma.W[1] = att_out_w; ma.Bv[1] = att_out_b; ma.C[1] = OA;
        gemm_multi_kernel<<<dim3(MROWS / 128, 2), 256, GEMM_SMEM>>>(ma, MROWS);
    }

    // ln1 of (x + oa + dtw + extra)
    lnsum4_kernel<<<MROWS / 8, 256>>>(x, OA, DTW, B1, lns + 0, lnb + 0, B4);

    // feed_forward1: up (relu) + split-K=4 down -> 4 partials; ln2 + senx mul
    GEMM(B4, ff1w1, ff1b1, HID, MROWS, FFD, DD, DD, 1);
    gemm_tf32_kernel<<<dim3(MROWS / 128, 1, 4), 256, GEMM_SMEM>>>(
        HID, ff1w2, ff1b2, PART, MROWS, DD, FFD / 4, FFD, (size_t)CHSZ, 0);
    ln2mul_kernel<<<MROWS / 8, 256>>>(PART, B4, SENX, lns + 128, lnb + 128, B2, B3);

    // feed_forward2: up (relu) + split-K=4 down; spatial_norm + residual
    GEMM(B3, ff2w1, ff2b1, HID, MROWS, FFD, DD, DD, 1);
    gemm_tf32_kernel<<<dim3(MROWS / 128, 1, 4), 256, GEMM_SMEM>>>(
        HID, ff2w2, ff2b2, PART, MROWS, DD, FFD / 4, FFD, (size_t)CHSZ, 0);
    final_kernel<<<MROWS / 8, 256>>>(PART, B2, lns + 2 * 128, lnb + 2 * 128, out);
#undef GEMM
}

// round 15
// speedup vs baseline: 1.7561x; 1.7561x over previous
#include <cuda_runtime.h>
#include <cstdint>

#define BB 8
#define TT 12
#define NNODE 400
#define DD 128
#define HH 8
#define HDIM 16
#define UU 16
#define CC 64
#define FFD 2048
#define MROWS (BB*TT*NNODE)   /* 38400 */
#define BTN (BB*TT)           /* 96 */

// ---- single scratch arena (no allocations allowed) ----
#define CHSZ 4915200u         /* MROWS*DD */
#define OFF_HID   (13u*CHSZ)
#define OFF_KP    (OFF_HID + (size_t)MROWS*FFD)
#define OFF_VP    (OFF_KP + (size_t)BTN*CC*DD)
#define OFF_SENX  (OFF_VP + (size_t)BTN*CC*DD)
#define SCRATCH_TOTAL (OFF_SENX + (size_t)NNODE*DD)

__device__ float g_scratch[SCRATCH_TOTAL];
__device__ float g_zerobias[FFD];   // static zero-init

// ---------------- tf32 helpers ---------------------------------------------
__device__ __forceinline__ unsigned cvt_tf32(float v) {
    unsigned r;
    asm("cvt.rna.tf32.f32 %0, %1;" : "=r"(r) : "f"(v));
    return r;
}
__device__ __forceinline__ void mma_tf32(float& c0, float& c1, float& c2, float& c3,
                                         unsigned a0, unsigned a1, unsigned a2, unsigned a3,
                                         unsigned b0, unsigned b1) {
    asm("mma.sync.aligned.m16n8k8.row.col.f32.tf32.tf32.f32 "
        "{%0,%1,%2,%3}, {%4,%5,%6,%7}, {%8,%9}, {%0,%1,%2,%3};"
        : "+f"(c0), "+f"(c1), "+f"(c2), "+f"(c3)
        : "r"(a0), "r"(a1), "r"(a2), "r"(a3), "r"(b0), "r"(b1));
}
__device__ __forceinline__ unsigned sm_u32(const void* p) {
    return (unsigned)__cvta_generic_to_shared(p);
}
__device__ __forceinline__ void cp16(unsigned dst, const float* src, int srcsize) {
    asm volatile("cp.async.ca.shared.global [%0], [%1], 16, %2;"
                 :: "r"(dst), "l"(src), "r"(srcsize));
}
__device__ __forceinline__ void cp_commit() {
    asm volatile("cp.async.commit_group;");
}
__device__ __forceinline__ void cp_wait1() {
    asm volatile("cp.async.wait_group 1;");
}

// ---------------- tf32 GEMM core (R8 known-best: 3-stage cp.async) ---------
#define AS_WORDS (128 * 20)
#define BS_WORDS (16 * 136)
#define STAGE_WORDS (AS_WORDS + BS_WORDS)
#define NSTAGE 3
#define GEMM_SMEM (STAGE_WORDS * NSTAGE * 4) /* 56832 B */

__device__ __forceinline__ void gemm_core(
    unsigned* smem_u,
    const float* __restrict__ A, const float* __restrict__ W,
    const float* __restrict__ bias, float* __restrict__ C,
    int M, int N, int kchunk, int lda, int relu, int m0, int n0, int k0)
{
    int tid = threadIdx.x;
    int warp = tid >> 5, lane = tid & 31;
    int g = lane >> 2, tg = lane & 3;
    int wm = warp >> 2, wn = warp & 3;            // 2 x 4
    int nk = kchunk >> 4;

    int arow = tid >> 1, akoff = (tid & 1) * 8;
    int asz = (m0 + arow < M) ? 16 : 0;
    int bc0 = tid * 2;
    int br0 = bc0 >> 5, bn0 = (bc0 & 31) * 4;
    int br1 = (bc0 + 1) >> 5, bn1 = ((bc0 + 1) & 31) * 4;

    float acc[4][4][4];
#pragma unroll
    for (int i = 0; i < 4; i++)
#pragma unroll
        for (int j = 0; j < 4; j++)
#pragma unroll
            for (int r = 0; r < 4; r++) acc[i][j][r] = 0.f;

#define ISSUE(kt) do {                                                        \
        unsigned* Asb = smem_u + ((kt) % NSTAGE) * STAGE_WORDS;               \
        unsigned* Bsb = Asb + AS_WORDS;                                       \
        const float* asrc = &A[(size_t)(m0 + arow) * lda + k0 + (kt) * 16 + akoff]; \
        cp16(sm_u32(&Asb[arow * 20 + akoff]),     asrc,     asz);             \
        cp16(sm_u32(&Asb[arow * 20 + akoff + 4]), asrc + 4, asz);             \
        cp16(sm_u32(&Bsb[br0 * 136 + bn0]),                                   \
             &W[(size_t)(k0 + (kt) * 16 + br0) * N + n0 + bn0], 16);          \
        cp16(sm_u32(&Bsb[br1 * 136 + bn1]),                                   \
             &W[(size_t)(k0 + (kt) * 16 + br1) * N + n0 + bn1], 16);          \
    } while (0)

#pragma unroll
    for (int s = 0; s < NSTAGE - 1; s++) {
        if (s < nk) ISSUE(s);
        cp_commit();
    }

    for (int kt = 0; kt < nk; kt++) {
        if (kt + NSTAGE - 1 < nk) ISSUE(kt + NSTAGE - 1);
        cp_commit();
        cp_wait1();
        __syncthreads();

        const unsigned* as = smem_u + (kt % NSTAGE) * STAGE_WORDS;
        const unsigned* bs = as + AS_WORDS;

#pragma unroll
        for (int step = 0; step < 2; step++) {
            int ko = step * 8;
            unsigned af[4][4];
#pragma unroll
            for (int ma = 0; ma < 4; ma++) {
                int r = wm * 64 + ma * 16 + g;
                af[ma][0] = cvt_tf32(__uint_as_float(as[r * 20 + ko + tg]));
                af[ma][1] = cvt_tf32(__uint_as_float(as[(r + 8) * 20 + ko + tg]));
                af[ma][2] = cvt_tf32(__uint_as_float(as[r * 20 + ko + tg + 4]));
                af[ma][3] = cvt_tf32(__uint_as_float(as[(r + 8) * 20 + ko + tg + 4]));
            }
            unsigned bf[4][2];
#pragma unroll
            for (int na = 0; na < 4; na++) {
                int nc = wn * 32 + na * 8 + g;
                bf[na][0] = cvt_tf32(__uint_as_float(bs[(ko + tg) * 136 + nc]));
                bf[na][1] = cvt_tf32(__uint_as_float(bs[(ko + tg + 4) * 136 + nc]));
            }
#pragma unroll
            for (int ma = 0; ma < 4; ma++)
#pragma unroll
                for (int na = 0; na < 4; na++)
                    mma_tf32(acc[ma][na][0], acc[ma][na][1], acc[ma][na][2], acc[ma][na][3],
                             af[ma][0], af[ma][1], af[ma][2], af[ma][3],
                             bf[na][0], bf[na][1]);
        }
        __syncthreads();
    }
#undef ISSUE

#pragma unroll
    for (int ma = 0; ma < 4; ma++) {
        int r0 = m0 + wm * 64 + ma * 16 + g;
        int r1 = r0 + 8;
#pragma unroll
        for (int na = 0; na < 4; na++) {
            int col = n0 + wn * 32 + na * 8 + tg * 2;
            float b0 = bias[col], b1 = bias[col + 1];
            float o0 = acc[ma][na][0] + b0, o1 = acc[ma][na][1] + b1;
            float o2 = acc[ma][na][2] + b0, o3 = acc[ma][na][3] + b1;
            if (relu) {
                o0 = fmaxf(o0, 0.f); o1 = fmaxf(o1, 0.f);
                o2 = fmaxf(o2, 0.f); o3 = fmaxf(o3, 0.f);
            }
            if (r0 < M) *(float2*)&C[(size_t)r0 * N + col] = make_float2(o0, o1);
            if (r1 < M) *(float2*)&C[(size_t)r1 * N + col] = make_float2(o2, o3);
        }
    }
}

// generic wrapper (split-K via blockIdx.z)
__global__ __launch_bounds__(256, 2) void gemm_tf32_kernel(
    const float* __restrict__ A, const float* __restrict__ W,
    const float* __restrict__ bias, float* __restrict__ C,
    int M, int N, int kchunk, int lda, size_t zstride, int relu)
{
    extern __shared__ unsigned smem_u[];
    const float* bp = (blockIdx.z == 0) ? bias : g_zerobias;
    gemm_core(smem_u, A, W, bp, C + (size_t)blockIdx.z * zstride,
              M, N, kchunk, lda, relu,
              blockIdx.x * 128, blockIdx.y * 128, blockIdx.z * kchunk);
}

// fused multi-GEMM wrapper: per-slot A/W/bias/C, N=K=lda=128
struct MultiArgs {
    const float* A[7];
    const float* W[7];
    const float* Bv[7];
    float* C[7];
};
__global__ __launch_bounds__(256, 2) void gemm_multi_kernel(MultiArgs ma, int M)
{
    extern __shared__ unsigned smem_u[];
    int j = blockIdx.y;
    gemm_core(smem_u, ma.A[j], ma.W[j], ma.Bv[j], ma.C[j],
              M, DD, DD, DD, 0, blockIdx.x * 128, 0, 0);
}

// ---------------- warp-per-row LayerNorm family ----------------------------
__device__ __forceinline__ float warp_sum(float v) {
#pragma unroll
    for (int o = 16; o; o >>= 1) v += __shfl_xor_sync(0xffffffffu, v, o);
    return v;
}
__device__ __forceinline__ float block_sum_128(float v, float* sb) {
#pragma unroll
    for (int o = 16; o; o >>= 1) v += __shfl_xor_sync(0xffffffffu, v, o);
    if ((threadIdx.x & 31) == 0) sb[threadIdx.x >> 5] = v;
    __syncthreads();
    float r = sb[0] + sb[1] + sb[2] + sb[3];
    __syncthreads();
    return r;
}

__global__ __launch_bounds__(256) void lnsum4_kernel(
    const float* __restrict__ x, const float* __restrict__ a,
    const float* __restrict__ bp, const float* __restrict__ c,
    const float* __restrict__ g, const float* __restrict__ be,
    float* __restrict__ outp)
{
    int warp = threadIdx.x >> 5, lane = threadIdx.x & 31;
    size_t row = (size_t)blockIdx.x * 8 + warp;
    size_t i = row * 128 + lane * 4;
    float4 v0 = *(const float4*)&x[i];
    float4 v1 = *(const float4*)&a[i];
    float4 v2 = *(const float4*)&bp[i];
    float4 v3 = *(const float4*)&c[i];
    float vx = v0.x + v1.x + v2.x + v3.x;
    float vy = v0.y + v1.y + v2.y + v3.y;
    float vz = v0.z + v1.z + v2.z + v3.z;
    float vw = v0.w + v1.w + v2.w + v3.w;
    float mean = warp_sum(vx + vy + vz + vw) * (1.f / 128.f);
    float dx = vx - mean, dy = vy - mean, dz = vz - mean, dw = vw - mean;
    float var = warp_sum(dx*dx + dy*dy + dz*dz + dw*dw) * (1.f / 128.f);
    float rs = rsqrtf(var + 1e-5f);
    float4 gg = *(const float4*)&g[lane * 4];
    float4 bb = *(const float4*)&be[lane * 4];
    *(float4*)&outp[i] = make_float4(dx*rs*gg.x + bb.x, dy*rs*gg.y + bb.y,
                                     dz*rs*gg.z + bb.z, dw*rs*gg.w + bb.w);
}

// attn2 = LN(sum of 4 split-K partials + s); spin = attn2 * senx[row%NNODE]
__global__ __launch_bounds__(256) void ln2mul_kernel(
    const float* __restrict__ parts, const float* __restrict__ s,
    const float* __restrict__ senx,
    const float* __restrict__ g, const float* __restrict__ be,
    float* __restrict__ attn2, float* __restrict__ spin)
{
    int warp = threadIdx.x >> 5, lane = threadIdx.x & 31;
    size_t row = (size_t)blockIdx.x * 8 + warp;
    size_t i = row * 128 + lane * 4;
    float4 sv = *(const float4*)&s[i];
    float vx = sv.x, vy = sv.y, vz = sv.z, vw = sv.w;
#pragma unroll
    for (int c = 0; c < 4; c++) {
        float4 p = *(const float4*)&parts[i + (size_t)c * CHSZ];
        vx += p.x; vy += p.y; vz += p.z; vw += p.w;
    }
    float mean = warp_sum(vx + vy + vz + vw) * (1.f / 128.f);
    float dx = vx - mean, dy = vy - mean, dz = vz - mean, dw = vw - mean;
    float var = warp_sum(dx*dx + dy*dy + dz*dz + dw*dw) * (1.f / 128.f);
    float rs = rsqrtf(var + 1e-5f);
    float4 gg = *(const float4*)&g[lane * 4];
    float4 bb = *(const float4*)&be[lane * 4];
    float ox = dx*rs*gg.x + bb.x, oy = dy*rs*gg.y + bb.y;
    float oz = dz*rs*gg.z + bb.z, ow = dw*rs*gg.w + bb.w;
    *(float4*)&attn2[i] = make_float4(ox, oy, oz, ow);
    float4 sx = *(const float4*)&senx[(size_t)(row % NNODE) * 128 + lane * 4];
    *(float4*)&spin[i] = make_float4(ox*sx.x, oy*sx.y, oz*sx.z, ow*sx.w);
}

// out = attn2 + LN(sum of 4 split-K partials)
__global__ __launch_bounds__(256) void final_kernel(
    const float* __restrict__ parts, const float* __restrict__ attn2,
    const float* __restrict__ g, const float* __restrict__ be,
    float* __restrict__ outp)
{
    int warp = threadIdx.x >> 5, lane = threadIdx.x & 31;
    size_t row = (size_t)blockIdx.x * 8 + warp;
    size_t i = row * 128 + lane * 4;
    float vx = 0.f, vy = 0.f, vz = 0.f, vw = 0.f;
#pragma unroll
    for (int c = 0; c < 4; c++) {
        float4 p = *(const float4*)&parts[i + (size_t)c * CHSZ];
        vx += p.x; vy += p.y; vz += p.z; vw += p.w;
    }
    float mean = warp_sum(vx + vy + vz + vw) * (1.f / 128.f);
    float dx = vx - mean, dy = vy - mean, dz = vz - mean, dw = vw - mean;
    float var = warp_sum(dx*dx + dy*dy + dz*dz + dw*dw) * (1.f / 128.f);
    float rs = rsqrtf(var + 1e-5f);
    float4 gg = *(const float4*)&g[lane * 4];
    float4 bb = *(const float4*)&be[lane * 4];
    float4 a2 = *(const float4*)&attn2[i];
    *(float4*)&outp[i] = make_float4(a2.x + dx*rs*gg.x + bb.x, a2.y + dy*rs*gg.y + bb.y,
                                     a2.z + dz*rs*gg.z + bb.z, a2.w + dw*rs*gg.w + bb.w);
}

// ---------------- fused sen path: spe@sw+b -> LN -> @shw+b -> edge ---------
__global__ __launch_bounds__(128) void sen_kernel(
    const float* __restrict__ spe,
    const float* __restrict__ sw, const float* __restrict__ sb_,
    const float* __restrict__ shw, const float* __restrict__ shb,
    const float* __restrict__ lg, const float* __restrict__ lb_,
    const float* __restrict__ ew, const float* __restrict__ eb,
    float* __restrict__ senx, float* __restrict__ outtail)
{
    __shared__ float A[128], Bs[128], Cs[128];
    __shared__ float red[4];
    int n = blockIdx.x, t = threadIdx.x;
    int h = t >> 4, u = t & 15;

    A[t] = spe[(size_t)n * 128 + t];
    __syncthreads();

    float acc = sb_[t];
#pragma unroll 8
    for (int k = 0; k < 128; k++) acc = fmaf(A[k], sw[k * 128 + t], acc);

    float mean = block_sum_128(acc, red) * (1.f / 128.f);
    float d = acc - mean;
    float var = block_sum_128(d * d, red) * (1.f / 128.f);
    float sen = d * rsqrtf(var + 1e-5f) * lg[t] + lb_[t];
    Bs[t] = sen;
    __syncthreads();

    float el = shb[t];
#pragma unroll 8
    for (int k = 0; k < 128; k++) el = fmaf(Bs[k], shw[k * 128 + t], el);
    A[t] = el;
    __syncthreads();

    float eacc = eb[u];
#pragma unroll
    for (int k = 0; k < 16; k++) eacc = fmaf(A[k * 8 + h], ew[k * 16 + u], eacc);
    Bs[t] = eacc;
    __syncthreads();
    float mx = -1e30f;
#pragma unroll
    for (int hh = 0; hh < 8; hh++) mx = fmaxf(mx, Bs[hh * 16 + u]);
    float sume = 0.f;
#pragma unroll
    for (int hh = 0; hh < 8; hh++) sume += __expf(Bs[hh * 16 + u] - mx);
    float a = __expf(eacc - mx) / sume;
    Cs[t] = a;
    __syncthreads();
    float rs = 0.f;
#pragma unroll
    for (int uu = 0; uu < 16; uu++) rs += Cs[h * 16 + uu];
    float a2 = a / rs;
    __syncthreads();
    A[t] = a2;
    __syncthreads();
    float y = eb[16 + u];
#pragma unroll
    for (int k = 0; k < 16; k++) y = fmaf(A[h * 16 + k], ew[256 + k * 16 + u], y);
    senx[(size_t)n * 128 + t] = y;
    outtail[(size_t)n * 128 + t] = y;
}

// ---------------- adaptive avg pool over node axis -------------------------
__global__ void pool_kernel(const float* __restrict__ Kin, const float* __restrict__ Vin,
                            float* __restrict__ Kp, float* __restrict__ Vp)
{
    int bt = blockIdx.x, c = blockIdx.y, d = threadIdx.x;
    int s = (c * NNODE) / CC;
    int e = ((c + 1) * NNODE + CC - 1) / CC;
    float inv = 1.f / (float)(e - s);
    float ak = 0.f, av = 0.f;
    for (int n = s; n < e; n++) {
        ak += Kin[((size_t)bt * NNODE + n) * DD + d];
        av += Vin[((size_t)bt * NNODE + n) * DD + d];
    }
    Kp[((size_t)bt * CC + c) * DD + d] = ak * inv;
    Vp[((size_t)bt * CC + c) * DD + d] = av * inv;
}

// ---------------- dtw attention v3: phase-split, probs in smem -------------
// 2 queries/pass (K/V amortized), score/prob lanes live in per-warp smem.
// Phase A regs ~ q(32); Phase B regs ~ acc(32): disjoint -> <=128 regs, 2 blk/SM.
#define ATTN_SMEM ((6400 + 6656 + 6656 + 8 * 832) * 4)   /* 105472 B */
__global__ __launch_bounds__(256, 2) void attn_dtw_kernel(
    const float* __restrict__ Q, const float* __restrict__ K,
    const float* __restrict__ V, float* __restrict__ O)
{
    extern __shared__ float sm[];
    float* Qs = sm;               // 400*16
    float* Kt = sm + 6400;        // 16*416
    float* Vt = sm + 13056;       // 16*416
    float* PB = sm + 19712;       // 8 warps * 832 (2 queries x 416)
    int bt = blockIdx.x, h = blockIdx.y;
    size_t base = ((size_t)bt * NNODE) * DD + h * HDIM;
    int tid = threadIdx.x;
    for (int e = tid; e < NNODE * 4; e += 256) {
        int q = e >> 2, d4 = (e & 3) << 2;
        float4 qv = *(const float4*)&Q[base + (size_t)q * DD + d4];
        float4 kv = *(const float4*)&K[base + (size_t)q * DD + d4];
        float4 vv = *(const float4*)&V[base + (size_t)q * DD + d4];
        *(float4*)&Qs[q * 16 + d4] = qv;
        Kt[(d4 + 0) * 416 + q] = kv.x; Kt[(d4 + 1) * 416 + q] = kv.y;
        Kt[(d4 + 2) * 416 + q] = kv.z; Kt[(d4 + 3) * 416 + q] = kv.w;
        Vt[(d4 + 0) * 416 + q] = vv.x; Vt[(d4 + 1) * 416 + q] = vv.y;
        Vt[(d4 + 2) * 416 + q] = vv.z; Vt[(d4 + 3) * 416 + q] = vv.w;
    }
    __syncthreads();
    int warp = tid >> 5, lane = tid & 31;
    float* pb = PB + warp * 832;
    for (int pp = warp; pp < NNODE / 2; pp += 8) {
        int qa = pp * 2;
        // ---- Phase A: scores -> smem, softmax in smem ----
        {
            float qva[16], qvb[16];
#pragma unroll
            for (int d = 0; d < 16; d++) {
                qva[d] = Qs[qa * 16 + d];
                qvb[d] = Qs[qa * 16 + 16 + d];
            }
            float mxa = -1e30f, mxb = -1e30f;
#pragma unroll
            for (int i = 0; i < 13; i++) {
                int j = lane + (i << 5);
                float s0 = -1e30f, s1 = -1e30f;
                if (j < NNODE) {
                    s0 = 0.f; s1 = 0.f;
#pragma unroll
                    for (int d = 0; d < 16; d++) {
                        float kv = Kt[d * 416 + j];
                        s0 = fmaf(qva[d], kv, s0);
                        s1 = fmaf(qvb[d], kv, s1);
                    }
                    s0 *= 0.25f; s1 *= 0.25f;
                }
                pb[i * 32 + lane] = s0;
                pb[416 + i * 32 + lane] = s1;
                mxa = fmaxf(mxa, s0); mxb = fmaxf(mxb, s1);
            }
#pragma unroll
            for (int o = 16; o; o >>= 1) {
                mxa = fmaxf(mxa, __shfl_xor_sync(0xffffffffu, mxa, o));
                mxb = fmaxf(mxb, __shfl_xor_sync(0xffffffffu, mxb, o));
            }
            float la = 0.f, lb = 0.f;
#pragma unroll
            for (int i = 0; i < 13; i++) {
                int j = lane + (i << 5);
                float pa = 0.f, pbv = 0.f;
                if (j < NNODE) {
                    pa  = __expf(pb[i * 32 + lane] - mxa);
                    pbv = __expf(pb[416 + i * 32 + lane] - mxb);
                }
                pb[i * 32 + lane] = pa;
                pb[416 + i * 32 + lane] = pbv;
                la += pa; lb += pbv;
            }
#pragma unroll
            for (int o = 16; o; o >>= 1) {
                la += __shfl_xor_sync(0xffffffffu, la, o);
                lb += __shfl_xor_sync(0xffffffffu, lb, o);
            }
            // stash 1/l in lane-private slot tail (reuse pb slots 400..415 safe?
            // slots 400..415 of each row are padding (j>=400 -> p=0) — but lanes
            // 16..31 of i=12 wrote zeros there; use registers via shfl instead:
            if (lane == 0) { pb[400] = la; pb[816] = lb; }
        }
        __syncwarp();
        // ---- Phase B: PV from smem probs ----
        {
            float la = pb[400], lb = pb[816];
            float acca[16], accb[16];
#pragma unroll
            for (int d = 0; d < 16; d++) { acca[d] = 0.f; accb[d] = 0.f; }
#pragma unroll
            for (int i = 0; i < 13; i++) {
                int j = lane + (i << 5);
                if (j < NNODE) {
                    float pa = pb[i * 32 + lane];
                    float pbv = pb[416 + i * 32 + lane];
#pragma unroll
                    for (int d = 0; d < 16; d++) {
                        float vv = Vt[d * 416 + j];
                        acca[d] = fmaf(pa, vv, acca[d]);
                        accb[d] = fmaf(pbv, vv, accb[d]);
                    }
                }
            }
#pragma unroll
            for (int d = 0; d < 16; d++) {
#pragma unroll
                for (int o = 16; o; o >>= 1) {
                    acca[d] += __shfl_xor_sync(0xffffffffu, acca[d], o);
                    accb[d] += __shfl_xor_sync(0xffffffffu, accb[d], o);
                }
            }
            if (lane < 16) {
                O[base + (size_t)qa * DD + lane]       = acca[lane] / la;
                O[base + (size_t)(qa + 1) * DD + lane] = accb[lane] / lb;
            }
        }
        __syncwarp();
    }
}

// ---------------- pooled attention: 64 keys + positional bias --------------
__global__ __launch_bounds__(256) void attn_adp_kernel(
    const float* __restrict__ Q, const float* __restrict__ Kp,
    const float* __restrict__ Vp, const float* __restrict__ pos,
    float* __restrict__ O)
{
    __shared__ float Qs[NNODE * 16];
    __shared__ float Kt[16 * 64];
    __shared__ float Vt[16 * 64];
    int bt = blockIdx.x, h = blockIdx.y, tid = threadIdx.x;
    size_t qbase = ((size_t)bt * NNODE) * DD + h * HDIM;
    size_t kbase = ((size_t)bt * CC) * DD + h * HDIM;
    for (int e = tid; e < NNODE * 4; e += 256) {
        int q = e >> 2, d4 = (e & 3) << 2;
        *(float4*)&Qs[q * 16 + d4] = *(const float4*)&Q[qbase + (size_t)q * DD + d4];
    }
    {
        int c = tid >> 2, d4 = (tid & 3) << 2;
        float4 kv = *(const float4*)&Kp[kbase + (size_t)c * DD + d4];
        float4 vv = *(const float4*)&Vp[kbase + (size_t)c * DD + d4];
        Kt[(d4 + 0) * 64 + c] = kv.x; Kt[(d4 + 1) * 64 + c] = kv.y;
        Kt[(d4 + 2) * 64 + c] = kv.z; Kt[(d4 + 3) * 64 + c] = kv.w;
        Vt[(d4 + 0) * 64 + c] = vv.x; Vt[(d4 + 1) * 64 + c] = vv.y;
        Vt[(d4 + 2) * 64 + c] = vv.z; Vt[(d4 + 3) * 64 + c] = vv.w;
    }
    __syncthreads();
    int warp = tid >> 5, lane = tid & 31;
    for (int pp = warp; pp < NNODE / 2; pp += 8) {
        int qa = pp * 2;
        float qva[16], qvb[16];
#pragma unroll
        for (int d = 0; d < 16; d++) {
            qva[d] = Qs[qa * 16 + d];
            qvb[d] = Qs[qa * 16 + 16 + d];
        }
        float s00 = 0.f, s01 = 0.f, s10 = 0.f, s11 = 0.f;
#pragma unroll
        for (int d = 0; d < 16; d++) {
            float k0 = Kt[d * 64 + lane], k1 = Kt[d * 64 + lane + 32];
            s00 = fmaf(qva[d], k0, s00); s01 = fmaf(qva[d], k1, s01);
            s10 = fmaf(qvb[d], k0, s10); s11 = fmaf(qvb[d], k1, s11);
        }
        s00 = s00 * 0.25f + pos[(size_t)qa * 64 + lane];
        s01 = s01 * 0.25f + pos[(size_t)qa * 64 + lane + 32];
        s10 = s10 * 0.25f + pos[(size_t)(qa + 1) * 64 + lane];
        s11 = s11 * 0.25f + pos[(size_t)(qa + 1) * 64 + lane + 32];
        float mxa = fmaxf(s00, s01), mxb = fmaxf(s10, s11);
#pragma unroll
        for (int o = 16; o; o >>= 1) {
            mxa = fmaxf(mxa, __shfl_xor_sync(0xffffffffu, mxa, o));
            mxb = fmaxf(mxb, __shfl_xor_sync(0xffffffffu, mxb, o));
        }
        float p00 = __expf(s00 - mxa), p01 = __expf(s01 - mxa);
        float p10 = __expf(s10 - mxb), p11 = __expf(s11 - mxb);
        float la = p00 + p01, lb = p10 + p11;
#pragma unroll
        for (int o = 16; o; o >>= 1) {
            la += __shfl_xor_sync(0xffffffffu, la, o);
            lb += __shfl_xor_sync(0xffffffffu, lb, o);
        }
        float acca[16], accb[16];
#pragma unroll
        for (int d = 0; d < 16; d++) {
            float v0 = Vt[d * 64 + lane], v1 = Vt[d * 64 + lane + 32];
            acca[d] = p00 * v0 + p01 * v1;
            accb[d] = p10 * v0 + p11 * v1;
        }
#pragma unroll
        for (int d = 0; d < 16; d++) {
#pragma unroll
            for (int o = 16; o; o >>= 1) {
                acca[d] += __shfl_xor_sync(0xffffffffu, acca[d], o);
                accb[d] += __shfl_xor_sync(0xffffffffu, accb[d], o);
            }
        }
        if (lane < 16) {
            O[qbase + (size_t)qa * DD + lane]       = acca[lane] / la;
            O[qbase + (size_t)(qa + 1) * DD + lane] = accb[lane] / lb;
        }
    }
}

// ---------------- GEANet node path (reshape-of-transpose perm) -------------
__global__ void node_kernel(const float* __restrict__ share, const float* __restrict__ nw,
                            const float* __restrict__ nb, float* __restrict__ extra)
{
    __shared__ float s0[128], s1[128], s2[128];
    int row = blockIdx.x;
    int b = row / (TT * NNODE), p = row % (TT * NNODE);
    int nn = p / TT, ll = p % TT;
    int t = threadIdx.x;
    int h = t >> 4, u = t & 15;
    s0[t] = share[(((size_t)b * TT + ll) * NNODE + nn) * 128 + t];
    __syncthreads();
    float acc = nb[u];
#pragma unroll
    for (int k = 0; k < 16; k++) acc = fmaf(s0[h * 16 + k], nw[k * 16 + u], acc);
    s1[t] = acc;
    __syncthreads();
    float mx = -1e30f;
#pragma unroll
    for (int hh = 0; hh < 8; hh++) mx = fmaxf(mx, s1[hh * 16 + u]);
    float sume = 0.f;
#pragma unroll
    for (int hh = 0; hh < 8; hh++) sume += __expf(s1[hh * 16 + u] - mx);
    float a = __expf(acc - mx) / sume;
    s2[t] = a;
    __syncthreads();
    float rs = 0.f;
#pragma unroll
    for (int uu = 0; uu < 16; uu++) rs += s2[h * 16 + uu];
    float a2 = a / rs;
    __syncthreads();
    s0[t] = a2;
    __syncthreads();
    float y = nb[16 + u];
#pragma unroll
    for (int k = 0; k < 16; k++) y = fmaf(s0[h * 16 + k], nw[256 + k * 16 + u], y);
    extra[(size_t)row * 128 + t] = y;
}

// ---------------- host orchestration ---------------------------------------
extern "C" void kernel_launch(void* const* d_in, const int* in_sizes, int n_in,
                              void* d_out, int out_size)
{
    const float* x         = (const float*)d_in[0];
    const float* spe       = (const float*)d_in[1];
    const float* dtw_qkv_w = (const float*)d_in[2];
    const float* dtw_qkv_b = (const float*)d_in[3];
    const float* dtw_out_w = (const float*)d_in[4];
    const float* dtw_out_b = (const float*)d_in[5];
    const float* att_qkv_w = (const float*)d_in[6];
    const float* att_qkv_b = (const float*)d_in[7];
    const float* att_out_w = (const float*)d_in[8];
    const float* att_out_b = (const float*)d_in[9];
    const float* adp_pos   = (const float*)d_in[10];
    const float* share_w   = (const float*)d_in[11];
    const float* share_b   = (const float*)d_in[12];
    const float* node_w    = (const float*)d_in[13];
    const float* node_b    = (const float*)d_in[14];
    const float* edge_w    = (const float*)d_in[15];
    const float* edge_b    = (const float*)d_in[16];
    const float* spatial_w = (const float*)d_in[17];
    const float* spatial_b = (const float*)d_in[18];
    const float* ff1w1     = (const float*)d_in[19];
    const float* ff1b1     = (const float*)d_in[20];
    const float* ff1w2     = (const float*)d_in[21];
    const float* ff1b2     = (const float*)d_in[22];
    const float* ff2w1     = (const float*)d_in[23];
    const float* ff2b1     = (const float*)d_in[24];
    const float* ff2w2     = (const float*)d_in[25];
    const float* ff2b2     = (const float*)d_in[26];
    const float* lns       = (const float*)d_in[27];
    const float* lnb       = (const float*)d_in[28];
    float* out = (float*)d_out;

    float* g = nullptr;
    { void* p; cudaGetSymbolAddress(&p, g_scratch); g = (float*)p; }
    float* PART = g + 0u * CHSZ;           // 4 split-K partials (chunks 0-3)
    float* Q1   = g + 0u * CHSZ;
    float* K1   = g + 1u * CHSZ;
    float* V1   = g + 2u * CHSZ;
    float* Q2   = g + 3u * CHSZ;
    float* K2   = g + 4u * CHSZ;
    float* V2   = g + 5u * CHSZ;
    float* SHR  = g + 6u * CHSZ;
    float* DTW  = g + 7u * CHSZ;
    float* OA   = g + 8u * CHSZ;
    float* B1   = g + 9u * CHSZ;
    float* B2   = g + 10u * CHSZ;
    float* B3   = g + 11u * CHSZ;
    float* B4   = g + 12u * CHSZ;
    float* HID  = g + OFF_HID;
    float* KP   = g + OFF_KP;
    float* VP   = g + OFF_VP;
    float* SENX = g + OFF_SENX;

    cudaFuncSetAttribute(attn_dtw_kernel,
                         cudaFuncAttributeMaxDynamicSharedMemorySize, ATTN_SMEM);
    cudaFuncSetAttribute(gemm_tf32_kernel,
                         cudaFuncAttributeMaxDynamicSharedMemorySize, GEMM_SMEM);
    cudaFuncSetAttribute(gemm_multi_kernel,
                         cudaFuncAttributeMaxDynamicSharedMemorySize, GEMM_SMEM);

#define GEMM(A_, W_, Bi_, C_, M_, N_, K_, LDA_, R_) \
    gemm_tf32_kernel<<<dim3(((M_) + 127) / 128, (N_) / 128, 1), 256, GEMM_SMEM>>>( \
        A_, W_, Bi_, C_, M_, N_, K_, LDA_, 0, R_)

    // fused QKV projections + GEANet share (one launch)
    {
        MultiArgs ma;
        for (int j = 0; j < 7; j++) ma.A[j] = x;
        ma.W[0] = dtw_qkv_w + 0 * DD * DD; ma.Bv[0] = dtw_qkv_b + 0 * DD; ma.C[0] = Q1;
        ma.W[1] = dtw_qkv_w + 1 * DD * DD; ma.Bv[1] = dtw_qkv_b + 1 * DD; ma.C[1] = K1;
        ma.W[2] = dtw_qkv_w + 2 * DD * DD; ma.Bv[2] = dtw_qkv_b + 2 * DD; ma.C[2] = V1;
        ma.W[3] = att_qkv_w + 0 * DD * DD; ma.Bv[3] = att_qkv_b + 0 * DD; ma.C[3] = Q2;
        ma.W[4] = att_qkv_w + 1 * DD * DD; ma.Bv[4] = att_qkv_b + 1 * DD; ma.C[4] = K2;
        ma.W[5] = att_qkv_w + 2 * DD * DD; ma.Bv[5] = att_qkv_b + 2 * DD; ma.C[5] = V2;
        ma.W[6] = share_w;                 ma.Bv[6] = share_b;            ma.C[6] = SHR;
        gemm_multi_kernel<<<dim3(MROWS / 128, 7), 256, GEMM_SMEM>>>(ma, MROWS);
    }

    // fused sen path
    sen_kernel<<<NNODE, 128>>>(spe, spatial_w, spatial_b, share_w, share_b,
                               lns + 3 * 128, lnb + 3 * 128, edge_w, edge_b,
                               SENX, out + (size_t)MROWS * DD);

    // GEANet node path
    node_kernel<<<MROWS, 128>>>(SHR, node_w, node_b, B1);

    // attentions (dtw -> B2, pooled -> B3), then merged dual out-projection
    attn_dtw_kernel<<<dim3(BTN, HH), 256, ATTN_SMEM>>>(Q1, K1, V1, B2);
    pool_kernel<<<dim3(BTN, CC), 128>>>(K2, V2, KP, VP);
    attn_adp_kernel<<<dim3(BTN, HH), 256>>>(Q2, KP, VP, adp_pos, B3);
    {
        MultiArgs ma;
        ma.A[0] = B2; ma.W[0] = dtw_out_w; ma.Bv[0] = dtw_out_b; ma.C[0] = DTW;
        ma.A[1] = B3; ma.W[1] = att_out_w; ma.Bv[1] = att_out_b; ma.C[1] = OA;
        gemm_multi_kernel<<<dim3(MROWS / 128, 2), 256, GEMM_SMEM>>>(ma, MROWS);
    }

    // ln1 of (x + oa + dtw + extra)
    lnsum4_kernel<<<MROWS / 8, 256>>>(x, OA, DTW, B1, lns + 0, lnb + 0, B4);

    // feed_forward1: up (relu) + split-K=4 down -> 4 partials; ln2 + senx mul
    GEMM(B4, ff1w1, ff1b1, HID, MROWS, FFD, DD, DD, 1);
    gemm_tf32_kernel<<<dim3(MROWS / 128, 1, 4), 256, GEMM_SMEM>>>(
        HID, ff1w2, ff1b2, PART, MROWS, DD, FFD / 4, FFD, (size_t)CHSZ, 0);
    ln2mul_kernel<<<MROWS / 8, 256>>>(PART, B4, SENX, lns + 128, lnb + 128, B2, B3);

    // feed_forward2: up (relu) + split-K=4 down; spatial_norm + residual
    GEMM(B3, ff2w1, ff2b1, HID, MROWS, FFD, DD, DD, 1);
    gemm_tf32_kernel<<<dim3(MROWS / 128, 1, 4), 256, GEMM_SMEM>>>(
        HID, ff2w2, ff2b2, PART, MROWS, DD, FFD / 4, FFD, (size_t)CHSZ, 0);
    final_kernel<<<MROWS / 8, 256>>>(PART, B2, lns + 2 * 128, lnb + 2 * 128, out);
#undef GEMM
}